// round 1
// baseline (speedup 1.0000x reference)
#include <cuda_runtime.h>
#include <cuda_bf16.h>

// Problem constants
#define B_SZ 4096
#define MAX_LEN 128
#define EMB_D 300
#define REP_D 600
#define HID 1000
#define NCLS 5

// Scratch (no cudaMalloc allowed)
__device__ float g_rep[B_SZ * REP_D];       // [4096, 600]
__device__ float g_hidden[B_SZ * HID];      // [4096, 1000]
__device__ int g_is64;

// ---------------------------------------------------------------------------
// dtype detection: lengths values are in [1,127]. If stored as int64, every
// odd 32-bit word (upper half) is 0. If int32, odd positions hold lengths>=1.
// ---------------------------------------------------------------------------
__global__ void detect_kernel(const unsigned* __restrict__ lengths_raw) {
    unsigned o = 0;
#pragma unroll 8
    for (int i = 0; i < 128; ++i) o |= lengths_raw[2 * i + 1];
    g_is64 = (o == 0) ? 1 : 0;
}

// ---------------------------------------------------------------------------
// Pooling: one block per batch row. Thread d (<300) owns one embedding dim.
// Indices staged in smem; per-t reads of emb row are fully coalesced (1200B).
// ---------------------------------------------------------------------------
__global__ void __launch_bounds__(320) pool_kernel(
    const void* __restrict__ xv, const void* __restrict__ lenv,
    const float* __restrict__ emb)
{
    __shared__ int idx_s[MAX_LEN];
    const int b = blockIdx.x;
    const int tid = threadIdx.x;
    const int is64 = g_is64;

    int len;
    if (is64) {
        len = (int)((const long long*)lenv)[b];
        if (tid < MAX_LEN)
            idx_s[tid] = (int)((const long long*)xv)[(long)b * MAX_LEN + tid];
    } else {
        len = ((const int*)lenv)[b];
        if (tid < MAX_LEN)
            idx_s[tid] = ((const int*)xv)[(long)b * MAX_LEN + tid];
    }
    __syncthreads();

    const int d = tid;
    if (d < EMB_D) {
        float s = 0.0f;
        float mx = -3.402823466e38f;   // float32 min (matches jnp.finfo(f32).min)
#pragma unroll 4
        for (int t = 0; t < len; ++t) {
            float v = __ldg(&emb[(long)idx_s[t] * EMB_D + d]);
            s += v;
            mx = fmaxf(mx, v);
        }
        g_rep[(long)b * REP_D + d]         = s / (float)len;
        g_rep[(long)b * REP_D + EMB_D + d] = mx;
    }
}

// ---------------------------------------------------------------------------
// GEMM1: hidden = relu(rep[4096,600] @ W1[600,1000] + b1)
// 128x128 tile, BK=8 (600 = 8*75, no K tail), 256 threads, 8x8 per thread.
// ---------------------------------------------------------------------------
#define BM 128
#define BN 128
#define BK 8

__global__ void __launch_bounds__(256) gemm1_kernel(
    const float* __restrict__ W1, const float* __restrict__ b1)
{
    __shared__ float As[BK][BM];
    __shared__ float Bs[BK][BN];

    const int tid = threadIdx.x;
    const int tx = tid & 15;
    const int ty = tid >> 4;
    const int m0 = blockIdx.y * BM;
    const int n0 = blockIdx.x * BN;

    // A-tile load mapping: 128x8 = 1024 floats = 1 float4/thread
    const int arow = tid >> 1;          // 0..127
    const int acol = (tid & 1) * 4;     // 0 or 4
    // B-tile load mapping: 8x128 = 1024 floats = 1 float4/thread
    const int brow = tid >> 5;          // 0..7
    const int bcol = (tid & 31) * 4;    // 0..124

    float acc[8][8];
#pragma unroll
    for (int i = 0; i < 8; ++i)
#pragma unroll
        for (int j = 0; j < 8; ++j) acc[i][j] = 0.0f;

    for (int k0 = 0; k0 < REP_D; k0 += BK) {
        // A: rep rows are 600 floats (16B aligned at k0+acol since 600%4==0)
        float4 av = *(const float4*)&g_rep[(long)(m0 + arow) * REP_D + k0 + acol];
        As[acol + 0][arow] = av.x;
        As[acol + 1][arow] = av.y;
        As[acol + 2][arow] = av.z;
        As[acol + 3][arow] = av.w;

        // B: W1 rows are 1000 floats (1000%4==0 -> float4 aligned); guard N tail
        {
            const int n = n0 + bcol;
            float4 bv;
            if (n + 3 < HID) {
                bv = *(const float4*)&W1[(long)(k0 + brow) * HID + n];
            } else {
                bv.x = (n + 0 < HID) ? W1[(long)(k0 + brow) * HID + n + 0] : 0.0f;
                bv.y = (n + 1 < HID) ? W1[(long)(k0 + brow) * HID + n + 1] : 0.0f;
                bv.z = (n + 2 < HID) ? W1[(long)(k0 + brow) * HID + n + 2] : 0.0f;
                bv.w = (n + 3 < HID) ? W1[(long)(k0 + brow) * HID + n + 3] : 0.0f;
            }
            *(float4*)&Bs[brow][bcol] = bv;
        }
        __syncthreads();

#pragma unroll
        for (int kk = 0; kk < BK; ++kk) {
            float a[8], bb[8];
            *(float4*)&a[0]  = *(const float4*)&As[kk][ty * 8];
            *(float4*)&a[4]  = *(const float4*)&As[kk][ty * 8 + 4];
            *(float4*)&bb[0] = *(const float4*)&Bs[kk][tx * 8];
            *(float4*)&bb[4] = *(const float4*)&Bs[kk][tx * 8 + 4];
#pragma unroll
            for (int i = 0; i < 8; ++i)
#pragma unroll
                for (int j = 0; j < 8; ++j)
                    acc[i][j] += a[i] * bb[j];
        }
        __syncthreads();
    }

    // Epilogue: bias + relu, guard N tail
#pragma unroll
    for (int i = 0; i < 8; ++i) {
        const int m = m0 + ty * 8 + i;
#pragma unroll
        for (int j = 0; j < 8; ++j) {
            const int n = n0 + tx * 8 + j;
            if (n < HID) {
                float v = acc[i][j] + __ldg(&b1[n]);
                g_hidden[(long)m * HID + n] = fmaxf(v, 0.0f);
            }
        }
    }
}

// ---------------------------------------------------------------------------
// GEMM2: out = hidden[4096,1000] @ W2[1000,5] + b2. One warp per row.
// ---------------------------------------------------------------------------
__global__ void __launch_bounds__(256) gemm2_kernel(
    const float* __restrict__ W2, const float* __restrict__ b2,
    float* __restrict__ out)
{
    const int gwarp = (blockIdx.x * blockDim.x + threadIdx.x) >> 5;
    const int lane = threadIdx.x & 31;
    if (gwarp >= B_SZ) return;

    const float* h = &g_hidden[(long)gwarp * HID];
    float a0 = 0.f, a1 = 0.f, a2 = 0.f, a3 = 0.f, a4 = 0.f;

    for (int k = lane; k < HID; k += 32) {
        const float hv = h[k];
        const float* w = &W2[(long)k * NCLS];
        a0 += hv * __ldg(&w[0]);
        a1 += hv * __ldg(&w[1]);
        a2 += hv * __ldg(&w[2]);
        a3 += hv * __ldg(&w[3]);
        a4 += hv * __ldg(&w[4]);
    }
#pragma unroll
    for (int off = 16; off > 0; off >>= 1) {
        a0 += __shfl_down_sync(0xffffffffu, a0, off);
        a1 += __shfl_down_sync(0xffffffffu, a1, off);
        a2 += __shfl_down_sync(0xffffffffu, a2, off);
        a3 += __shfl_down_sync(0xffffffffu, a3, off);
        a4 += __shfl_down_sync(0xffffffffu, a4, off);
    }
    if (lane == 0) {
        out[(long)gwarp * NCLS + 0] = a0 + __ldg(&b2[0]);
        out[(long)gwarp * NCLS + 1] = a1 + __ldg(&b2[1]);
        out[(long)gwarp * NCLS + 2] = a2 + __ldg(&b2[2]);
        out[(long)gwarp * NCLS + 3] = a3 + __ldg(&b2[3]);
        out[(long)gwarp * NCLS + 4] = a4 + __ldg(&b2[4]);
    }
}

// ---------------------------------------------------------------------------
extern "C" void kernel_launch(void* const* d_in, const int* in_sizes, int n_in,
                              void* d_out, int out_size)
{
    const void*  x       = d_in[0];
    const void*  lengths = d_in[1];
    const float* emb     = (const float*)d_in[2];
    const float* W1      = (const float*)d_in[3];
    const float* b1      = (const float*)d_in[4];
    const float* W2      = (const float*)d_in[5];
    const float* b2      = (const float*)d_in[6];
    float* out = (float*)d_out;

    detect_kernel<<<1, 1>>>((const unsigned*)lengths);

    pool_kernel<<<B_SZ, 320>>>(x, lengths, emb);

    dim3 g1((HID + BN - 1) / BN, B_SZ / BM);   // (8, 32)
    gemm1_kernel<<<g1, 256>>>(W1, b1);

    gemm2_kernel<<<(B_SZ * 32) / 256, 256>>>(W2, b2, out);
}

// round 3
// speedup vs baseline: 1.6428x; 1.6428x over previous
#include <cuda_runtime.h>
#include <cuda_bf16.h>
#include <cstdint>

// Problem constants
#define B_SZ 4096
#define MAX_LEN 128
#define EMB_D 300
#define REP_D 600
#define HID 1000
#define NCLS 5

#define KPAD 640      // 600 padded to 10 chunks of 64
#define NPAD 1024     // 1000 padded to 8 tiles of 128
#define NCHUNK_K 10   // per term
#define NTERMS 3
#define NCHUNK (NCHUNK_K * NTERMS)   // 30

// ---------------------------------------------------------------------------
// Scratch (no cudaMalloc allowed)
// ---------------------------------------------------------------------------
__device__ __align__(128) __nv_bfloat16 g_a_hi[B_SZ * KPAD];   // rep hi  [4096,640]
__device__ __align__(128) __nv_bfloat16 g_a_lo[B_SZ * KPAD];   // rep lo
__device__ __align__(128) __nv_bfloat16 g_b_hi[NPAD * KPAD];   // W1^T hi [1024,640]
__device__ __align__(128) __nv_bfloat16 g_b_lo[NPAD * KPAD];   // W1^T lo
__device__ int g_is64;

// ---------------------------------------------------------------------------
// PTX helpers (family-portable: ldmatrix / mma.sync / cp.async)
// ---------------------------------------------------------------------------
__device__ __forceinline__ uint32_t smem_u32(const void* p) {
    uint32_t a;
    asm("{ .reg .u64 t; cvta.to.shared.u64 t, %1; cvt.u32.u64 %0, t; }"
        : "=r"(a) : "l"(p));
    return a;
}

__device__ __forceinline__ void cp_async16(uint32_t smem_dst, const void* gmem_src) {
    asm volatile("cp.async.ca.shared.global [%0], [%1], 16;"
                 :: "r"(smem_dst), "l"(gmem_src));
}
#define CP_COMMIT() asm volatile("cp.async.commit_group;" ::: "memory")
#define CP_WAIT(n)  asm volatile("cp.async.wait_group %0;" :: "n"(n) : "memory")

__device__ __forceinline__ void ldsm4(uint32_t* r, uint32_t addr) {
    asm volatile("ldmatrix.sync.aligned.m8n8.x4.shared.b16 {%0,%1,%2,%3}, [%4];"
                 : "=r"(r[0]), "=r"(r[1]), "=r"(r[2]), "=r"(r[3]) : "r"(addr));
}

__device__ __forceinline__ void mma16816(float* c, const uint32_t* a, const uint32_t* b) {
    asm volatile(
        "mma.sync.aligned.m16n8k16.row.col.f32.bf16.bf16.f32 "
        "{%0,%1,%2,%3}, {%4,%5,%6,%7}, {%8,%9}, {%0,%1,%2,%3};"
        : "+f"(c[0]), "+f"(c[1]), "+f"(c[2]), "+f"(c[3])
        : "r"(a[0]), "r"(a[1]), "r"(a[2]), "r"(a[3]), "r"(b[0]), "r"(b[1]));
}

// ---------------------------------------------------------------------------
// dtype detection: lengths in [1,127]; int64 => all upper 32-bit words zero.
// ---------------------------------------------------------------------------
__global__ void detect_kernel(const unsigned* __restrict__ lengths_raw) {
    unsigned o = 0;
#pragma unroll 8
    for (int i = 0; i < 128; ++i) o |= lengths_raw[2 * i + 1];
    g_is64 = (o == 0) ? 1 : 0;
}

// ---------------------------------------------------------------------------
// Pooling: one block per batch row, thread d owns one embedding dim.
// Emits bf16 hi/lo split of rep (cols 0..299 avg, 300..599 max, pad zeros).
// ---------------------------------------------------------------------------
__global__ void __launch_bounds__(320) pool_kernel(
    const void* __restrict__ xv, const void* __restrict__ lenv,
    const float* __restrict__ emb)
{
    __shared__ int idx_s[MAX_LEN];
    const int b = blockIdx.x;
    const int tid = threadIdx.x;
    const int is64 = g_is64;

    int len;
    if (is64) {
        len = (int)((const long long*)lenv)[b];
        if (tid < MAX_LEN)
            idx_s[tid] = (int)((const long long*)xv)[(long)b * MAX_LEN + tid];
    } else {
        len = ((const int*)lenv)[b];
        if (tid < MAX_LEN)
            idx_s[tid] = ((const int*)xv)[(long)b * MAX_LEN + tid];
    }
    __syncthreads();

    const long rowb = (long)b * KPAD;
    if (tid < 40) {
        g_a_hi[rowb + REP_D + tid] = __float2bfloat16(0.0f);
        g_a_lo[rowb + REP_D + tid] = __float2bfloat16(0.0f);
    }

    const int d = tid;
    if (d < EMB_D) {
        float s = 0.0f;
        float mx = -3.402823466e38f;
#pragma unroll 4
        for (int t = 0; t < len; ++t) {
            float v = __ldg(&emb[(long)idx_s[t] * EMB_D + d]);
            s += v;
            mx = fmaxf(mx, v);
        }
        float avg = s / (float)len;

        __nv_bfloat16 ah = __float2bfloat16(avg);
        g_a_hi[rowb + d] = ah;
        g_a_lo[rowb + d] = __float2bfloat16(avg - __bfloat162float(ah));

        __nv_bfloat16 mh = __float2bfloat16(mx);
        g_a_hi[rowb + EMB_D + d] = mh;
        g_a_lo[rowb + EMB_D + d] = __float2bfloat16(mx - __bfloat162float(mh));
    }
}

// ---------------------------------------------------------------------------
// W1 [600,1000] fp32 -> transposed padded bf16 hi/lo [1024,640] (K-major rows)
// ---------------------------------------------------------------------------
__global__ void __launch_bounds__(256) convert_w1_kernel(const float* __restrict__ W1) {
    int idx = blockIdx.x * blockDim.x + threadIdx.x;
    if (idx >= NPAD * KPAD) return;
    int n = idx % NPAD;
    int k = idx / NPAD;
    float v = (n < HID && k < REP_D) ? __ldg(&W1[(long)k * HID + n]) : 0.0f;
    __nv_bfloat16 hi = __float2bfloat16(v);
    g_b_hi[(long)n * KPAD + k] = hi;
    g_b_lo[(long)n * KPAD + k] = __float2bfloat16(v - __bfloat162float(hi));
}

// ---------------------------------------------------------------------------
// out init: out[m,c] = b2[c] (atomics accumulate on top)
// ---------------------------------------------------------------------------
__global__ void __launch_bounds__(256) init_out_kernel(const float* __restrict__ b2,
                                                       float* __restrict__ out) {
    int i = blockIdx.x * blockDim.x + threadIdx.x;
    if (i < B_SZ * NCLS) out[i] = __ldg(&b2[i % NCLS]);
}

// ---------------------------------------------------------------------------
// Fused GEMM1 (bf16x3 via mma.sync) + bias + ReLU + GEMM2
// CTA tile M=128,N=128; 8 warps (2m x 4n), warp tile 64x32; BK=64, 30 chunks.
// smem: double-buffered A/B tiles, 72-half padded stride (conflict-free ldsm).
// ---------------------------------------------------------------------------
#define BK 64
#define LDS 72                       // halves per smem row (64 + 8 pad)
#define TILE_BYTES (128 * LDS * 2)   // 18432
#define SA0 0u
#define SB0 (SA0 + TILE_BYTES)
#define SA1 (SB0 + TILE_BYTES)
#define SB1 (SA1 + TILE_BYTES)
#define SMEM_BYTES (SB1 + TILE_BYTES)   // 73728

__device__ __forceinline__ void chunk_srcs(int c, int m0, int n0,
                                           const __nv_bfloat16*& A,
                                           const __nv_bfloat16*& Bp) {
    const int t = c / NCHUNK_K;
    const int kk = (c % NCHUNK_K) * BK;
    A  = ((t == 1) ? g_a_lo : g_a_hi) + (long)m0 * KPAD + kk;
    Bp = ((t == 2) ? g_b_lo : g_b_hi) + (long)n0 * KPAD + kk;
}

__global__ void __launch_bounds__(256) mma_kernel(
    const float* __restrict__ b1, const float* __restrict__ W2,
    float* __restrict__ out)
{
    extern __shared__ __align__(128) char smem[];
    const uint32_t sb = smem_u32(smem);
    const int tid  = threadIdx.x;
    const int wid  = tid >> 5;
    const int lane = tid & 31;
    const int warp_m = wid >> 2;      // 0..1
    const int warp_n = wid & 3;       // 0..3
    const int n0 = blockIdx.x * 128;
    const int m0 = blockIdx.y * 128;

    // --- fill helper mappings (4 x 16B chunks per tile per thread) ---
    // e = tid + i*256 in [0,1024): row = e>>3, seg = e&7
    // smem off = (row*LDS + seg*8)*2 ; gmem off = row*KPAD + seg*8

    float acc[4][4][4];
#pragma unroll
    for (int a = 0; a < 4; ++a)
#pragma unroll
        for (int b = 0; b < 4; ++b)
#pragma unroll
            for (int d = 0; d < 4; ++d) acc[a][b][d] = 0.0f;

    // Prefetch chunk 0
    {
        const __nv_bfloat16 *gA, *gB;
        chunk_srcs(0, m0, n0, gA, gB);
#pragma unroll
        for (int i = 0; i < 4; ++i) {
            const int e = tid + i * 256;
            const int row = e >> 3, seg = e & 7;
            const uint32_t so = (uint32_t)(row * LDS + seg * 8) * 2;
            const long go = (long)row * KPAD + seg * 8;
            cp_async16(sb + SA0 + so, gA + go);
            cp_async16(sb + SB0 + so, gB + go);
        }
        CP_COMMIT();
    }

    // ldmatrix per-lane address components (within tile, in halves)
    const int a_row16 = (lane & 7) + ((lane >> 3) & 1) * 8;   // row within 16
    const int a_koff  = (lane >> 4) * 8;                      // 0 or 8
    const int b_n16   = (lane & 7) + (lane >> 4) * 8;         // n within 16
    const int b_koff  = ((lane >> 3) & 1) * 8;                // 0 or 8

    for (int c = 0; c < NCHUNK; ++c) {
        const uint32_t sa = (c & 1) ? SA1 : SA0;
        const uint32_t sbf = (c & 1) ? SB1 : SB0;

        if (c + 1 < NCHUNK) {
            const uint32_t na = (c & 1) ? SA0 : SA1;
            const uint32_t nb = (c & 1) ? SB0 : SB1;
            const __nv_bfloat16 *gA, *gB;
            chunk_srcs(c + 1, m0, n0, gA, gB);
#pragma unroll
            for (int i = 0; i < 4; ++i) {
                const int e = tid + i * 256;
                const int row = e >> 3, seg = e & 7;
                const uint32_t so = (uint32_t)(row * LDS + seg * 8) * 2;
                const long go = (long)row * KPAD + seg * 8;
                cp_async16(sb + na + so, gA + go);
                cp_async16(sb + nb + so, gB + go);
            }
            CP_COMMIT();
            CP_WAIT(1);
        } else {
            CP_WAIT(0);
        }
        __syncthreads();

#pragma unroll
        for (int ks = 0; ks < BK / 16; ++ks) {
            const int k0 = ks * 16;
            uint32_t af[4][4];
            uint32_t bf[4][2];
#pragma unroll
            for (int mf = 0; mf < 4; ++mf) {
                const int row = warp_m * 64 + mf * 16 + a_row16;
                ldsm4(af[mf], sb + sa + (uint32_t)(row * LDS + k0 + a_koff) * 2);
            }
#pragma unroll
            for (int nf2 = 0; nf2 < 2; ++nf2) {
                uint32_t r[4];
                const int nrow = warp_n * 32 + nf2 * 16 + b_n16;
                ldsm4(r, sb + sbf + (uint32_t)(nrow * LDS + k0 + b_koff) * 2);
                bf[nf2 * 2 + 0][0] = r[0]; bf[nf2 * 2 + 0][1] = r[1];
                bf[nf2 * 2 + 1][0] = r[2]; bf[nf2 * 2 + 1][1] = r[3];
            }
#pragma unroll
            for (int mf = 0; mf < 4; ++mf)
#pragma unroll
                for (int nf = 0; nf < 4; ++nf)
                    mma16816(acc[mf][nf], af[mf], bf[nf]);
        }
        __syncthreads();
    }

    // --- Fused epilogue: bias + relu + W2 dot + atomic accumulate ---
    float* w2s = (float*)(smem);            // 128*5 floats
    float* b1s = (float*)(smem + 2560);     // 128 floats
    for (int i = tid; i < 128 * NCLS; i += 256) {
        const int n = n0 + i / NCLS;
        w2s[i] = (n < HID) ? __ldg(&W2[(long)n * NCLS + (i % NCLS)]) : 0.0f;
    }
    if (tid < 128) {
        const int n = n0 + tid;
        b1s[tid] = (n < HID) ? __ldg(&b1[n]) : 0.0f;
    }
    __syncthreads();

#pragma unroll
    for (int mf = 0; mf < 4; ++mf) {
#pragma unroll
        for (int h = 0; h < 2; ++h) {
            const int m = m0 + warp_m * 64 + mf * 16 + (lane >> 2) + 8 * h;
            float p0 = 0.f, p1 = 0.f, p2 = 0.f, p3 = 0.f, p4 = 0.f;
#pragma unroll
            for (int nf = 0; nf < 4; ++nf) {
                const int nl = warp_n * 32 + nf * 8 + 2 * (lane & 3);
                const float v0 = fmaxf(acc[mf][nf][2 * h + 0] + b1s[nl], 0.0f);
                const float v1 = fmaxf(acc[mf][nf][2 * h + 1] + b1s[nl + 1], 0.0f);
                p0 += v0 * w2s[nl * NCLS + 0] + v1 * w2s[(nl + 1) * NCLS + 0];
                p1 += v0 * w2s[nl * NCLS + 1] + v1 * w2s[(nl + 1) * NCLS + 1];
                p2 += v0 * w2s[nl * NCLS + 2] + v1 * w2s[(nl + 1) * NCLS + 2];
                p3 += v0 * w2s[nl * NCLS + 3] + v1 * w2s[(nl + 1) * NCLS + 3];
                p4 += v0 * w2s[nl * NCLS + 4] + v1 * w2s[(nl + 1) * NCLS + 4];
            }
#pragma unroll
            for (int off = 1; off <= 2; off <<= 1) {
                p0 += __shfl_xor_sync(0xffffffffu, p0, off);
                p1 += __shfl_xor_sync(0xffffffffu, p1, off);
                p2 += __shfl_xor_sync(0xffffffffu, p2, off);
                p3 += __shfl_xor_sync(0xffffffffu, p3, off);
                p4 += __shfl_xor_sync(0xffffffffu, p4, off);
            }
            if ((lane & 3) == 0) {
                atomicAdd(&out[(long)m * NCLS + 0], p0);
                atomicAdd(&out[(long)m * NCLS + 1], p1);
                atomicAdd(&out[(long)m * NCLS + 2], p2);
                atomicAdd(&out[(long)m * NCLS + 3], p3);
                atomicAdd(&out[(long)m * NCLS + 4], p4);
            }
        }
    }
}

// ---------------------------------------------------------------------------
extern "C" void kernel_launch(void* const* d_in, const int* in_sizes, int n_in,
                              void* d_out, int out_size)
{
    const void*  x       = d_in[0];
    const void*  lengths = d_in[1];
    const float* emb     = (const float*)d_in[2];
    const float* W1      = (const float*)d_in[3];
    const float* b1      = (const float*)d_in[4];
    const float* W2      = (const float*)d_in[5];
    const float* b2      = (const float*)d_in[6];
    float* out = (float*)d_out;

    cudaFuncSetAttribute(mma_kernel, cudaFuncAttributeMaxDynamicSharedMemorySize,
                         (int)SMEM_BYTES);

    detect_kernel<<<1, 1>>>((const unsigned*)lengths);
    pool_kernel<<<B_SZ, 320>>>(x, lengths, emb);
    convert_w1_kernel<<<(NPAD * KPAD + 255) / 256, 256>>>(W1);
    init_out_kernel<<<(B_SZ * NCLS + 255) / 256, 256>>>(b2, out);

    dim3 g(NPAD / 128, B_SZ / 128);   // (8, 32)
    mma_kernel<<<g, 256, SMEM_BYTES>>>(b1, W2, out);
}

// round 4
// speedup vs baseline: 2.3152x; 1.4093x over previous
#include <cuda_runtime.h>
#include <cuda_bf16.h>
#include <cstdint>

// Problem constants
#define B_SZ 4096
#define MAX_LEN 128
#define EMB_D 300
#define REP_D 600
#define HID 1000
#define NCLS 5

#define KPAD 640      // 600 padded to 10 chunks of 64
#define NPAD 1024     // 1000 padded to 8 tiles of 128
#define NCHUNK_K 10

// ---------------------------------------------------------------------------
// Scratch (no cudaMalloc allowed)
// ---------------------------------------------------------------------------
__device__ __align__(128) __nv_bfloat16 g_a_hi[B_SZ * KPAD];   // rep hi  [4096,640]
__device__ __align__(128) __nv_bfloat16 g_a_lo[B_SZ * KPAD];   // rep lo
__device__ __align__(128) __nv_bfloat16 g_b_hi[NPAD * KPAD];   // W1^T hi [1024,640]
__device__ __align__(128) __nv_bfloat16 g_b_lo[NPAD * KPAD];   // W1^T lo

// ---------------------------------------------------------------------------
// PTX helpers (family-portable: ldmatrix / mma.sync / cp.async)
// ---------------------------------------------------------------------------
__device__ __forceinline__ uint32_t smem_u32(const void* p) {
    uint32_t a;
    asm("{ .reg .u64 t; cvta.to.shared.u64 t, %1; cvt.u32.u64 %0, t; }"
        : "=r"(a) : "l"(p));
    return a;
}

__device__ __forceinline__ void cp_async16(uint32_t smem_dst, const void* gmem_src) {
    asm volatile("cp.async.ca.shared.global [%0], [%1], 16;"
                 :: "r"(smem_dst), "l"(gmem_src));
}
#define CP_COMMIT() asm volatile("cp.async.commit_group;" ::: "memory")
#define CP_WAIT(n)  asm volatile("cp.async.wait_group %0;" :: "n"(n) : "memory")

__device__ __forceinline__ void ldsm4(uint32_t* r, uint32_t addr) {
    asm volatile("ldmatrix.sync.aligned.m8n8.x4.shared.b16 {%0,%1,%2,%3}, [%4];"
                 : "=r"(r[0]), "=r"(r[1]), "=r"(r[2]), "=r"(r[3]) : "r"(addr));
}

__device__ __forceinline__ void mma16816(float* c, const uint32_t* a, const uint32_t* b) {
    asm volatile(
        "mma.sync.aligned.m16n8k16.row.col.f32.bf16.bf16.f32 "
        "{%0,%1,%2,%3}, {%4,%5,%6,%7}, {%8,%9}, {%0,%1,%2,%3};"
        : "+f"(c[0]), "+f"(c[1]), "+f"(c[2]), "+f"(c[3])
        : "r"(a[0]), "r"(a[1]), "r"(a[2]), "r"(a[3]), "r"(b[0]), "r"(b[1]));
}

// ---------------------------------------------------------------------------
// Pooling + self dtype-detect + out init.
// One block per batch row. Thread d owns one embedding dim.
// lengths in [1,127]: raw word[1]==0 <=> int64 layout.
// ---------------------------------------------------------------------------
__global__ void __launch_bounds__(320) pool_kernel(
    const void* __restrict__ xv, const void* __restrict__ lenv,
    const float* __restrict__ emb, const float* __restrict__ b2,
    float* __restrict__ out)
{
    __shared__ int idx_s[MAX_LEN];
    const int b = blockIdx.x;
    const int tid = threadIdx.x;

    // self-detect dtype (one extra 4B load, L2-hit after first block)
    const int is64 = (((const unsigned*)lenv)[1] == 0u);

    int len;
    if (is64) {
        len = (int)((const long long*)lenv)[b];
        if (tid < MAX_LEN)
            idx_s[tid] = (int)((const long long*)xv)[(long)b * MAX_LEN + tid];
    } else {
        len = ((const int*)lenv)[b];
        if (tid < MAX_LEN)
            idx_s[tid] = ((const int*)xv)[(long)b * MAX_LEN + tid];
    }
    __syncthreads();

    const long rowb = (long)b * KPAD;
    if (tid < 40) {
        g_a_hi[rowb + REP_D + tid] = __float2bfloat16(0.0f);
        g_a_lo[rowb + REP_D + tid] = __float2bfloat16(0.0f);
    }
    // out init: out[b][c] = b2[c]; mma accumulates atomically afterwards
    if (tid >= 64 && tid < 64 + NCLS)
        out[(long)b * NCLS + (tid - 64)] = __ldg(&b2[tid - 64]);

    const int d = tid;
    if (d < EMB_D) {
        float s = 0.0f;
        float mx = -3.402823466e38f;
#pragma unroll 4
        for (int t = 0; t < len; ++t) {
            float v = __ldg(&emb[(long)idx_s[t] * EMB_D + d]);
            s += v;
            mx = fmaxf(mx, v);
        }
        float avg = s / (float)len;

        __nv_bfloat16 ah = __float2bfloat16(avg);
        g_a_hi[rowb + d] = ah;
        g_a_lo[rowb + d] = __float2bfloat16(avg - __bfloat162float(ah));

        __nv_bfloat16 mh = __float2bfloat16(mx);
        g_a_hi[rowb + EMB_D + d] = mh;
        g_a_lo[rowb + EMB_D + d] = __float2bfloat16(mx - __bfloat162float(mh));
    }
}

// ---------------------------------------------------------------------------
// W1 [600,1000] fp32 -> transposed padded bf16 hi/lo [1024,640]
// smem 32x32 tile transpose: coalesced reads AND writes.
// Grid: (KPAD/32, NPAD/32) = (20, 32), block (32, 8).
// ---------------------------------------------------------------------------
__global__ void __launch_bounds__(256) convert_w1_kernel(const float* __restrict__ W1) {
    __shared__ float tile[32][33];
    const int k0 = blockIdx.x * 32;
    const int n0 = blockIdx.y * 32;
    const int tx = threadIdx.x;   // 0..31
    const int ty = threadIdx.y;   // 0..7

#pragma unroll
    for (int i = 0; i < 4; ++i) {
        const int k = k0 + ty + i * 8;
        const int n = n0 + tx;
        tile[ty + i * 8][tx] = (k < REP_D && n < HID) ? __ldg(&W1[(long)k * HID + n]) : 0.0f;
    }
    __syncthreads();

#pragma unroll
    for (int i = 0; i < 4; ++i) {
        const int n = n0 + ty + i * 8;
        const int k = k0 + tx;
        const float v = tile[tx][ty + i * 8];
        const __nv_bfloat16 hi = __float2bfloat16(v);
        g_b_hi[(long)n * KPAD + k] = hi;
        g_b_lo[(long)n * KPAD + k] = __float2bfloat16(v - __bfloat162float(hi));
    }
}

// ---------------------------------------------------------------------------
// Fused GEMM1 (bf16x3 emulated fp32 via mma.sync) + bias + ReLU + GEMM2.
// CTA tile M=128,N=128; 8 warps (2m x 4n), warp tile 64x32.
// Per k-chunk (BK=64): load A_hi/A_lo/B_hi/B_lo tiles ONCE, run 3 terms:
//   acc += Ahi*Bhi + Ahi*Blo + Alo*Bhi   (A frags reused in registers)
// Single smem buffer (73.7KB) -> 2 CTAs/SM, grid 256 CTAs = one wave.
// ---------------------------------------------------------------------------
#define BK 64
#define LDS 72                       // halves per smem row (64 + 8 pad)
#define TILE_BYTES (128 * LDS * 2)   // 18432
#define SA_HI 0u
#define SA_LO (SA_HI + TILE_BYTES)
#define SB_HI (SA_LO + TILE_BYTES)
#define SB_LO (SB_HI + TILE_BYTES)
#define SMEM_BYTES (SB_LO + TILE_BYTES)   // 73728

__global__ void __launch_bounds__(256, 2) mma_kernel(
    const float* __restrict__ b1, const float* __restrict__ W2,
    float* __restrict__ out)
{
    extern __shared__ __align__(128) char smem[];
    const uint32_t sb = smem_u32(smem);
    const int tid  = threadIdx.x;
    const int wid  = tid >> 5;
    const int lane = tid & 31;
    const int warp_m = wid >> 2;      // 0..1
    const int warp_n = wid & 3;       // 0..3
    const int n0 = blockIdx.x * 128;
    const int m0 = blockIdx.y * 128;

    const __nv_bfloat16* gah = g_a_hi + (long)m0 * KPAD;
    const __nv_bfloat16* gal = g_a_lo + (long)m0 * KPAD;
    const __nv_bfloat16* gbh = g_b_hi + (long)n0 * KPAD;
    const __nv_bfloat16* gbl = g_b_lo + (long)n0 * KPAD;

    float acc[4][4][4];
#pragma unroll
    for (int a = 0; a < 4; ++a)
#pragma unroll
        for (int b = 0; b < 4; ++b)
#pragma unroll
            for (int d = 0; d < 4; ++d) acc[a][b][d] = 0.0f;

    // ldmatrix per-lane address components (within tile, in halves)
    const int a_row16 = (lane & 7) + ((lane >> 3) & 1) * 8;   // row within 16
    const int a_koff  = (lane >> 4) * 8;                      // 0 or 8
    const int b_n16   = (lane & 7) + (lane >> 4) * 8;         // n within 16
    const int b_koff  = ((lane >> 3) & 1) * 8;                // 0 or 8

    for (int c = 0; c < NCHUNK_K; ++c) {
        const int kc = c * BK;

        // Fill all 4 tiles (each: 128 rows x 64 halves; 4 x 16B per thread)
#pragma unroll
        for (int i = 0; i < 4; ++i) {
            const int e = tid + i * 256;
            const int row = e >> 3, seg = e & 7;
            const uint32_t so = (uint32_t)(row * LDS + seg * 8) * 2;
            const long go = (long)row * KPAD + kc + seg * 8;
            cp_async16(sb + SA_HI + so, gah + go);
            cp_async16(sb + SA_LO + so, gal + go);
            cp_async16(sb + SB_HI + so, gbh + go);
            cp_async16(sb + SB_LO + so, gbl + go);
        }
        CP_COMMIT();
        CP_WAIT(0);
        __syncthreads();

#pragma unroll
        for (int ks = 0; ks < BK / 16; ++ks) {
            const int k0 = ks * 16;
            uint32_t af[4][4];      // reused: first A_hi, then A_lo
            uint32_t bh[4][2], bl[4][2];

            // B_hi + B_lo fragments
#pragma unroll
            for (int nf2 = 0; nf2 < 2; ++nf2) {
                const uint32_t boff =
                    (uint32_t)((warp_n * 32 + nf2 * 16 + b_n16) * LDS + k0 + b_koff) * 2;
                uint32_t r[4];
                ldsm4(r, sb + SB_HI + boff);
                bh[nf2 * 2 + 0][0] = r[0]; bh[nf2 * 2 + 0][1] = r[1];
                bh[nf2 * 2 + 1][0] = r[2]; bh[nf2 * 2 + 1][1] = r[3];
                ldsm4(r, sb + SB_LO + boff);
                bl[nf2 * 2 + 0][0] = r[0]; bl[nf2 * 2 + 0][1] = r[1];
                bl[nf2 * 2 + 1][0] = r[2]; bl[nf2 * 2 + 1][1] = r[3];
            }

            // A_hi fragments: terms hi*hi and hi*lo
#pragma unroll
            for (int mf = 0; mf < 4; ++mf) {
                const uint32_t aoff =
                    (uint32_t)((warp_m * 64 + mf * 16 + a_row16) * LDS + k0 + a_koff) * 2;
                ldsm4(af[mf], sb + SA_HI + aoff);
            }
#pragma unroll
            for (int mf = 0; mf < 4; ++mf)
#pragma unroll
                for (int nf = 0; nf < 4; ++nf) {
                    mma16816(acc[mf][nf], af[mf], bh[nf]);
                    mma16816(acc[mf][nf], af[mf], bl[nf]);
                }

            // A_lo fragments (overwrite af): term lo*hi
#pragma unroll
            for (int mf = 0; mf < 4; ++mf) {
                const uint32_t aoff =
                    (uint32_t)((warp_m * 64 + mf * 16 + a_row16) * LDS + k0 + a_koff) * 2;
                ldsm4(af[mf], sb + SA_LO + aoff);
            }
#pragma unroll
            for (int mf = 0; mf < 4; ++mf)
#pragma unroll
                for (int nf = 0; nf < 4; ++nf)
                    mma16816(acc[mf][nf], af[mf], bh[nf]);
        }
        __syncthreads();
    }

    // --- Fused epilogue: bias + relu + W2 dot + atomic accumulate ---
    float* w2s = (float*)(smem);            // 128*5 floats
    float* b1s = (float*)(smem + 2560);     // 128 floats
    for (int i = tid; i < 128 * NCLS; i += 256) {
        const int n = n0 + i / NCLS;
        w2s[i] = (n < HID) ? __ldg(&W2[(long)n * NCLS + (i % NCLS)]) : 0.0f;
    }
    if (tid < 128) {
        const int n = n0 + tid;
        b1s[tid] = (n < HID) ? __ldg(&b1[n]) : 0.0f;
    }
    __syncthreads();

#pragma unroll
    for (int mf = 0; mf < 4; ++mf) {
#pragma unroll
        for (int h = 0; h < 2; ++h) {
            const int m = m0 + warp_m * 64 + mf * 16 + (lane >> 2) + 8 * h;
            float p0 = 0.f, p1 = 0.f, p2 = 0.f, p3 = 0.f, p4 = 0.f;
#pragma unroll
            for (int nf = 0; nf < 4; ++nf) {
                const int nl = warp_n * 32 + nf * 8 + 2 * (lane & 3);
                const float v0 = fmaxf(acc[mf][nf][2 * h + 0] + b1s[nl], 0.0f);
                const float v1 = fmaxf(acc[mf][nf][2 * h + 1] + b1s[nl + 1], 0.0f);
                p0 += v0 * w2s[nl * NCLS + 0] + v1 * w2s[(nl + 1) * NCLS + 0];
                p1 += v0 * w2s[nl * NCLS + 1] + v1 * w2s[(nl + 1) * NCLS + 1];
                p2 += v0 * w2s[nl * NCLS + 2] + v1 * w2s[(nl + 1) * NCLS + 2];
                p3 += v0 * w2s[nl * NCLS + 3] + v1 * w2s[(nl + 1) * NCLS + 3];
                p4 += v0 * w2s[nl * NCLS + 4] + v1 * w2s[(nl + 1) * NCLS + 4];
            }
#pragma unroll
            for (int off = 1; off <= 2; off <<= 1) {
                p0 += __shfl_xor_sync(0xffffffffu, p0, off);
                p1 += __shfl_xor_sync(0xffffffffu, p1, off);
                p2 += __shfl_xor_sync(0xffffffffu, p2, off);
                p3 += __shfl_xor_sync(0xffffffffu, p3, off);
                p4 += __shfl_xor_sync(0xffffffffu, p4, off);
            }
            if ((lane & 3) == 0) {
                atomicAdd(&out[(long)m * NCLS + 0], p0);
                atomicAdd(&out[(long)m * NCLS + 1], p1);
                atomicAdd(&out[(long)m * NCLS + 2], p2);
                atomicAdd(&out[(long)m * NCLS + 3], p3);
                atomicAdd(&out[(long)m * NCLS + 4], p4);
            }
        }
    }
}

// ---------------------------------------------------------------------------
extern "C" void kernel_launch(void* const* d_in, const int* in_sizes, int n_in,
                              void* d_out, int out_size)
{
    const void*  x       = d_in[0];
    const void*  lengths = d_in[1];
    const float* emb     = (const float*)d_in[2];
    const float* W1      = (const float*)d_in[3];
    const float* b1      = (const float*)d_in[4];
    const float* W2      = (const float*)d_in[5];
    const float* b2      = (const float*)d_in[6];
    float* out = (float*)d_out;

    cudaFuncSetAttribute(mma_kernel, cudaFuncAttributeMaxDynamicSharedMemorySize,
                         (int)SMEM_BYTES);

    pool_kernel<<<B_SZ, 320>>>(x, lengths, emb, b2, out);

    dim3 cb(32, 8);
    dim3 cg(KPAD / 32, NPAD / 32);   // (20, 32)
    convert_w1_kernel<<<cg, cb>>>(W1);

    dim3 g(NPAD / 128, B_SZ / 128);  // (8, 32)
    mma_kernel<<<g, 256, SMEM_BYTES>>>(b1, W2, out);
}

// round 5
// speedup vs baseline: 2.3645x; 1.0213x over previous
#include <cuda_runtime.h>
#include <cuda_bf16.h>
#include <cstdint>

// Problem constants
#define B_SZ 4096
#define MAX_LEN 128
#define EMB_D 300
#define REP_D 600
#define HID 1000
#define NCLS 5

#define KPAD 640      // 600 padded to 20 chunks of 32
#define NPAD 1024     // 1000 padded to 8 tiles of 128
#define BK 32
#define NCHUNK (KPAD / BK)   // 20

// ---------------------------------------------------------------------------
// Scratch (no cudaMalloc allowed)
// ---------------------------------------------------------------------------
__device__ __align__(128) __nv_bfloat16 g_a_hi[B_SZ * KPAD];   // rep hi  [4096,640]
__device__ __align__(128) __nv_bfloat16 g_a_lo[B_SZ * KPAD];   // rep lo
__device__ __align__(128) __nv_bfloat16 g_b_hi[NPAD * KPAD];   // W1^T hi [1024,640]
__device__ __align__(128) __nv_bfloat16 g_b_lo[NPAD * KPAD];   // W1^T lo

// ---------------------------------------------------------------------------
// PTX helpers (family-portable: ldmatrix / mma.sync / cp.async)
// ---------------------------------------------------------------------------
__device__ __forceinline__ uint32_t smem_u32(const void* p) {
    uint32_t a;
    asm("{ .reg .u64 t; cvta.to.shared.u64 t, %1; cvt.u32.u64 %0, t; }"
        : "=r"(a) : "l"(p));
    return a;
}

__device__ __forceinline__ void cp_async16(uint32_t smem_dst, const void* gmem_src) {
    asm volatile("cp.async.ca.shared.global [%0], [%1], 16;"
                 :: "r"(smem_dst), "l"(gmem_src));
}
#define CP_COMMIT() asm volatile("cp.async.commit_group;" ::: "memory")
#define CP_WAIT(n)  asm volatile("cp.async.wait_group %0;" :: "n"(n) : "memory")

__device__ __forceinline__ void ldsm4(uint32_t* r, uint32_t addr) {
    asm volatile("ldmatrix.sync.aligned.m8n8.x4.shared.b16 {%0,%1,%2,%3}, [%4];"
                 : "=r"(r[0]), "=r"(r[1]), "=r"(r[2]), "=r"(r[3]) : "r"(addr));
}

__device__ __forceinline__ void mma16816(float* c, const uint32_t* a,
                                         uint32_t b0, uint32_t b1) {
    asm volatile(
        "mma.sync.aligned.m16n8k16.row.col.f32.bf16.bf16.f32 "
        "{%0,%1,%2,%3}, {%4,%5,%6,%7}, {%8,%9}, {%0,%1,%2,%3};"
        : "+f"(c[0]), "+f"(c[1]), "+f"(c[2]), "+f"(c[3])
        : "r"(a[0]), "r"(a[1]), "r"(a[2]), "r"(a[3]), "r"(b0), "r"(b1));
}

// ---------------------------------------------------------------------------
// Pooling (float4) + self dtype-detect + out init.
// One block (80 threads) per batch row; tx<75 owns one float4 of dims.
// lengths in [1,127]: raw word[1]==0 <=> int64 layout.
// ---------------------------------------------------------------------------
__global__ void __launch_bounds__(80) pool_kernel(
    const void* __restrict__ xv, const void* __restrict__ lenv,
    const float* __restrict__ emb, const float* __restrict__ b2,
    float* __restrict__ out)
{
    __shared__ int idx_s[MAX_LEN];
    const int b = blockIdx.x;
    const int tid = threadIdx.x;

    const int is64 = (((const unsigned*)lenv)[1] == 0u);

    int len;
    if (is64) {
        len = (int)((const long long*)lenv)[b];
        for (int i = tid; i < len; i += 80)
            idx_s[i] = (int)((const long long*)xv)[(long)b * MAX_LEN + i];
    } else {
        len = ((const int*)lenv)[b];
        for (int i = tid; i < len; i += 80)
            idx_s[i] = ((const int*)xv)[(long)b * MAX_LEN + i];
    }
    __syncthreads();

    const long rowb = (long)b * KPAD;

    // out init: out[b][c] = b2[c]; mma accumulates atomically afterwards
    if (tid < NCLS)
        out[(long)b * NCLS + tid] = __ldg(&b2[tid]);

    if (tid >= 75) {
        // zero K padding cols 600..639 (5 threads x 8 elems)
        const int d0 = REP_D + (tid - 75) * 8;
#pragma unroll
        for (int j = 0; j < 8; ++j) {
            g_a_hi[rowb + d0 + j] = __float2bfloat16(0.0f);
            g_a_lo[rowb + d0 + j] = __float2bfloat16(0.0f);
        }
        return;
    }

    const float4* base = (const float4*)emb;   // emb rows: 75 float4 each
    float4 s  = make_float4(0.f, 0.f, 0.f, 0.f);
    float4 mx = make_float4(-3.402823466e38f, -3.402823466e38f,
                            -3.402823466e38f, -3.402823466e38f);
#pragma unroll 4
    for (int t = 0; t < len; ++t) {
        const float4 v = __ldg(&base[(long)idx_s[t] * 75 + tid]);
        s.x += v.x; s.y += v.y; s.z += v.z; s.w += v.w;
        mx.x = fmaxf(mx.x, v.x); mx.y = fmaxf(mx.y, v.y);
        mx.z = fmaxf(mx.z, v.z); mx.w = fmaxf(mx.w, v.w);
    }
    const float inv = 1.0f / (float)len;
    const float a0 = s.x * inv, a1 = s.y * inv, a2 = s.z * inv, a3 = s.w * inv;

    // hi/lo split, packed 4-bf16 (8B) stores
    const int d = 4 * tid;
    {
        __nv_bfloat16 h0 = __float2bfloat16(a0), h1 = __float2bfloat16(a1);
        __nv_bfloat16 h2 = __float2bfloat16(a2), h3 = __float2bfloat16(a3);
        __nv_bfloat162 p0(h0, h1), p1(h2, h3);
        *(uint2*)&g_a_hi[rowb + d] =
            make_uint2(*(uint32_t*)&p0, *(uint32_t*)&p1);
        __nv_bfloat162 q0(__float2bfloat16(a0 - __bfloat162float(h0)),
                          __float2bfloat16(a1 - __bfloat162float(h1)));
        __nv_bfloat162 q1(__float2bfloat16(a2 - __bfloat162float(h2)),
                          __float2bfloat16(a3 - __bfloat162float(h3)));
        *(uint2*)&g_a_lo[rowb + d] =
            make_uint2(*(uint32_t*)&q0, *(uint32_t*)&q1);
    }
    {
        __nv_bfloat16 h0 = __float2bfloat16(mx.x), h1 = __float2bfloat16(mx.y);
        __nv_bfloat16 h2 = __float2bfloat16(mx.z), h3 = __float2bfloat16(mx.w);
        __nv_bfloat162 p0(h0, h1), p1(h2, h3);
        *(uint2*)&g_a_hi[rowb + EMB_D + d] =
            make_uint2(*(uint32_t*)&p0, *(uint32_t*)&p1);
        __nv_bfloat162 q0(__float2bfloat16(mx.x - __bfloat162float(h0)),
                          __float2bfloat16(mx.y - __bfloat162float(h1)));
        __nv_bfloat162 q1(__float2bfloat16(mx.z - __bfloat162float(h2)),
                          __float2bfloat16(mx.w - __bfloat162float(h3)));
        *(uint2*)&g_a_lo[rowb + EMB_D + d] =
            make_uint2(*(uint32_t*)&q0, *(uint32_t*)&q1);
    }
}

// ---------------------------------------------------------------------------
// W1 [600,1000] fp32 -> transposed padded bf16 hi/lo [1024,640]
// smem 32x32 tile transpose: coalesced reads AND writes.
// ---------------------------------------------------------------------------
__global__ void __launch_bounds__(256) convert_w1_kernel(const float* __restrict__ W1) {
    __shared__ float tile[32][33];
    const int k0 = blockIdx.x * 32;
    const int n0 = blockIdx.y * 32;
    const int tx = threadIdx.x;   // 0..31
    const int ty = threadIdx.y;   // 0..7

#pragma unroll
    for (int i = 0; i < 4; ++i) {
        const int k = k0 + ty + i * 8;
        const int n = n0 + tx;
        tile[ty + i * 8][tx] = (k < REP_D && n < HID) ? __ldg(&W1[(long)k * HID + n]) : 0.0f;
    }
    __syncthreads();

#pragma unroll
    for (int i = 0; i < 4; ++i) {
        const int n = n0 + ty + i * 8;
        const int k = k0 + tx;
        const float v = tile[tx][ty + i * 8];
        const __nv_bfloat16 hi = __float2bfloat16(v);
        g_b_hi[(long)n * KPAD + k] = hi;
        g_b_lo[(long)n * KPAD + k] = __float2bfloat16(v - __bfloat162float(hi));
    }
}

// ---------------------------------------------------------------------------
// Fused GEMM1 (bf16x3 emulated fp32 via mma.sync) + bias + ReLU + GEMM2.
// CTA tile M=128,N=128; 8 warps (2m x 4n), warp tile 64x32.
// BK=32, 20 chunks, DOUBLE-BUFFERED smem stages (2 CTAs/SM + intra-CTA overlap).
// Per chunk: acc += Ahi*Bhi + Ahi*Blo + Alo*Bhi (A frags resident per pass).
// ---------------------------------------------------------------------------
#define LDSH 40                       // halves per smem row (32 + 8 pad)
#define TILE_B (128 * LDSH * 2)       // 10240
#define STAGE_B (4 * TILE_B)          // 40960: [A_HI, A_LO, B_HI, B_LO]
#define SMEM_BYTES (2 * STAGE_B)      // 81920

__device__ __forceinline__ void fill_stage(
    uint32_t sbase, int tid, int kc,
    const __nv_bfloat16* gah, const __nv_bfloat16* gal,
    const __nv_bfloat16* gbh, const __nv_bfloat16* gbl)
{
#pragma unroll
    for (int i = 0; i < 2; ++i) {
        const int e = tid + i * 256;
        const int row = e >> 2, seg = e & 3;
        const uint32_t so = (uint32_t)(row * LDSH + seg * 8) * 2;
        const long go = (long)row * KPAD + kc + seg * 8;
        cp_async16(sbase + 0 * TILE_B + so, gah + go);
        cp_async16(sbase + 1 * TILE_B + so, gal + go);
        cp_async16(sbase + 2 * TILE_B + so, gbh + go);
        cp_async16(sbase + 3 * TILE_B + so, gbl + go);
    }
}

__global__ void __launch_bounds__(256, 2) mma_kernel(
    const float* __restrict__ b1, const float* __restrict__ W2,
    float* __restrict__ out)
{
    extern __shared__ __align__(128) char smem[];
    const uint32_t sb = smem_u32(smem);
    const int tid  = threadIdx.x;
    const int wid  = tid >> 5;
    const int lane = tid & 31;
    const int warp_m = wid >> 2;      // 0..1
    const int warp_n = wid & 3;       // 0..3
    const int n0 = blockIdx.x * 128;
    const int m0 = blockIdx.y * 128;

    const __nv_bfloat16* gah = g_a_hi + (long)m0 * KPAD;
    const __nv_bfloat16* gal = g_a_lo + (long)m0 * KPAD;
    const __nv_bfloat16* gbh = g_b_hi + (long)n0 * KPAD;
    const __nv_bfloat16* gbl = g_b_lo + (long)n0 * KPAD;

    float acc[4][4][4];
#pragma unroll
    for (int a = 0; a < 4; ++a)
#pragma unroll
        for (int b = 0; b < 4; ++b)
#pragma unroll
            for (int d = 0; d < 4; ++d) acc[a][b][d] = 0.0f;

    // ldmatrix per-lane address components (in halves)
    const int a_row16 = (lane & 7) + ((lane >> 3) & 1) * 8;
    const int a_koff  = (lane >> 4) * 8;
    const int b_n16   = (lane & 7) + (lane >> 4) * 8;
    const int b_koff  = ((lane >> 3) & 1) * 8;

    fill_stage(sb, tid, 0, gah, gal, gbh, gbl);
    CP_COMMIT();

    for (int c = 0; c < NCHUNK; ++c) {
        const uint32_t cur = sb + (uint32_t)(c & 1) * STAGE_B;

        if (c + 1 < NCHUNK) {
            fill_stage(sb + (uint32_t)((c + 1) & 1) * STAGE_B, tid,
                       (c + 1) * BK, gah, gal, gbh, gbl);
            CP_COMMIT();
            CP_WAIT(1);
        } else {
            CP_WAIT(0);
        }
        __syncthreads();

#pragma unroll
        for (int ks = 0; ks < BK / 16; ++ks) {
            const int k0 = ks * 16;
            uint32_t af[4][4];

            // ---- pass 1: A_hi x (B_hi, B_lo) ----
#pragma unroll
            for (int mf = 0; mf < 4; ++mf)
                ldsm4(af[mf], cur + 0 * TILE_B +
                      (uint32_t)((warp_m * 64 + mf * 16 + a_row16) * LDSH + k0 + a_koff) * 2);
#pragma unroll
            for (int nf2 = 0; nf2 < 2; ++nf2) {
                const uint32_t boff =
                    (uint32_t)((warp_n * 32 + nf2 * 16 + b_n16) * LDSH + k0 + b_koff) * 2;
                uint32_t r[4];
                ldsm4(r, cur + 2 * TILE_B + boff);
#pragma unroll
                for (int mf = 0; mf < 4; ++mf) {
                    mma16816(acc[mf][nf2 * 2 + 0], af[mf], r[0], r[1]);
                    mma16816(acc[mf][nf2 * 2 + 1], af[mf], r[2], r[3]);
                }
                ldsm4(r, cur + 3 * TILE_B + boff);
#pragma unroll
                for (int mf = 0; mf < 4; ++mf) {
                    mma16816(acc[mf][nf2 * 2 + 0], af[mf], r[0], r[1]);
                    mma16816(acc[mf][nf2 * 2 + 1], af[mf], r[2], r[3]);
                }
            }

            // ---- pass 2: A_lo x B_hi ----
#pragma unroll
            for (int mf = 0; mf < 4; ++mf)
                ldsm4(af[mf], cur + 1 * TILE_B +
                      (uint32_t)((warp_m * 64 + mf * 16 + a_row16) * LDSH + k0 + a_koff) * 2);
#pragma unroll
            for (int nf2 = 0; nf2 < 2; ++nf2) {
                const uint32_t boff =
                    (uint32_t)((warp_n * 32 + nf2 * 16 + b_n16) * LDSH + k0 + b_koff) * 2;
                uint32_t r[4];
                ldsm4(r, cur + 2 * TILE_B + boff);
#pragma unroll
                for (int mf = 0; mf < 4; ++mf) {
                    mma16816(acc[mf][nf2 * 2 + 0], af[mf], r[0], r[1]);
                    mma16816(acc[mf][nf2 * 2 + 1], af[mf], r[2], r[3]);
                }
            }
        }
        __syncthreads();
    }

    // --- Fused epilogue: bias + relu + W2 dot + atomic accumulate ---
    float* w2s = (float*)(smem);            // 128*5 floats
    float* b1s = (float*)(smem + 2560);     // 128 floats
    for (int i = tid; i < 128 * NCLS; i += 256) {
        const int n = n0 + i / NCLS;
        w2s[i] = (n < HID) ? __ldg(&W2[(long)n * NCLS + (i % NCLS)]) : 0.0f;
    }
    if (tid < 128) {
        const int n = n0 + tid;
        b1s[tid] = (n < HID) ? __ldg(&b1[n]) : 0.0f;
    }
    __syncthreads();

#pragma unroll
    for (int mf = 0; mf < 4; ++mf) {
#pragma unroll
        for (int h = 0; h < 2; ++h) {
            const int m = m0 + warp_m * 64 + mf * 16 + (lane >> 2) + 8 * h;
            float p0 = 0.f, p1 = 0.f, p2 = 0.f, p3 = 0.f, p4 = 0.f;
#pragma unroll
            for (int nf = 0; nf < 4; ++nf) {
                const int nl = warp_n * 32 + nf * 8 + 2 * (lane & 3);
                const float v0 = fmaxf(acc[mf][nf][2 * h + 0] + b1s[nl], 0.0f);
                const float v1 = fmaxf(acc[mf][nf][2 * h + 1] + b1s[nl + 1], 0.0f);
                p0 += v0 * w2s[nl * NCLS + 0] + v1 * w2s[(nl + 1) * NCLS + 0];
                p1 += v0 * w2s[nl * NCLS + 1] + v1 * w2s[(nl + 1) * NCLS + 1];
                p2 += v0 * w2s[nl * NCLS + 2] + v1 * w2s[(nl + 1) * NCLS + 2];
                p3 += v0 * w2s[nl * NCLS + 3] + v1 * w2s[(nl + 1) * NCLS + 3];
                p4 += v0 * w2s[nl * NCLS + 4] + v1 * w2s[(nl + 1) * NCLS + 4];
            }
#pragma unroll
            for (int off = 1; off <= 2; off <<= 1) {
                p0 += __shfl_xor_sync(0xffffffffu, p0, off);
                p1 += __shfl_xor_sync(0xffffffffu, p1, off);
                p2 += __shfl_xor_sync(0xffffffffu, p2, off);
                p3 += __shfl_xor_sync(0xffffffffu, p3, off);
                p4 += __shfl_xor_sync(0xffffffffu, p4, off);
            }
            if ((lane & 3) == 0) {
                atomicAdd(&out[(long)m * NCLS + 0], p0);
                atomicAdd(&out[(long)m * NCLS + 1], p1);
                atomicAdd(&out[(long)m * NCLS + 2], p2);
                atomicAdd(&out[(long)m * NCLS + 3], p3);
                atomicAdd(&out[(long)m * NCLS + 4], p4);
            }
        }
    }
}

// ---------------------------------------------------------------------------
extern "C" void kernel_launch(void* const* d_in, const int* in_sizes, int n_in,
                              void* d_out, int out_size)
{
    const void*  x       = d_in[0];
    const void*  lengths = d_in[1];
    const float* emb     = (const float*)d_in[2];
    const float* W1      = (const float*)d_in[3];
    const float* b1      = (const float*)d_in[4];
    const float* W2      = (const float*)d_in[5];
    const float* b2      = (const float*)d_in[6];
    float* out = (float*)d_out;

    cudaFuncSetAttribute(mma_kernel, cudaFuncAttributeMaxDynamicSharedMemorySize,
                         (int)SMEM_BYTES);

    pool_kernel<<<B_SZ, 80>>>(x, lengths, emb, b2, out);

    dim3 cb(32, 8);
    dim3 cg(KPAD / 32, NPAD / 32);   // (20, 32)
    convert_w1_kernel<<<cg, cb>>>(W1);

    dim3 g(NPAD / 128, B_SZ / 128);  // (8, 32)
    mma_kernel<<<g, 256, SMEM_BYTES>>>(b1, W2, out);
}